// round 5
// baseline (speedup 1.0000x reference)
#include <cuda_runtime.h>
#include <cuda_bf16.h>
#include <math.h>

// ---------------- problem constants ----------------
#define B_SZ   256
#define T_SZ   512
#define HID    300
#define EMB    300
#define VOCAB  50000
#define NCLS   5
#define GATES  1200        // 4*HID
#define PCOLS  2400        // 2*GATES (A-part | B-part)

// recurrence persistent-kernel tiling
#define NCTA   120         // 8 b-tiles x 15 u-tiles (<= 148 SMs, 1 CTA/SM)
#define BT     32          // batch rows per CTA
#define UT     20          // hidden units per CTA
#define RT     80          // 4 gates * UT rows per CTA
#define KZ     4           // internal K split
#define KC     75          // K chunk (4*75 = 300)

// ---------------- static device scratch (no allocations allowed) -------------
__device__ float d_P[(long long)VOCAB * PCOLS];     // 480 MB: glove @ [A|B]^T
__device__ float d_Wcat[PCOLS * EMB];               // repacked W_ih
__device__ float d_h[2 * B_SZ * HID];               // double-buffered h
__device__ float d_hsum[B_SZ * HID];                // sum_t h_t
__device__ unsigned int g_barcnt;
__device__ unsigned int g_bargen;

// ---------------- prep: repack W_ih, zero h0, reset grid barrier -------------
// Wcat rows 0..1199    = W_ih[:, 0:300]   (A part, multiplies emb_t)
// Wcat rows 1200..2399 = W_ih[:, 300:600] (B part, multiplies emb_{t-1})
__global__ void prep_kernel(const float* __restrict__ W_ih,
                            float* __restrict__ Wcat,
                            float* __restrict__ h0) {
    int i = blockIdx.x * blockDim.x + threadIdx.x;
    if (i < PCOLS * EMB) {
        int n = i / EMB, k = i % EMB;
        Wcat[i] = (n < GATES) ? W_ih[n * 600 + k]
                              : W_ih[(n - GATES) * 600 + 300 + k];
    }
    if (i < B_SZ * HID) h0[i] = 0.f;
    if (i == 0) { g_barcnt = 0u; g_bargen = 0u; }
}

// ---------------- generic C = A @ B^T (fp32, 128x128 tile, 8x8 micro) --------
// (unchanged from the verified-correct R3 kernel; used only for the P GEMM)
#define TILE 128
#define KB   10
__global__ __launch_bounds__(256)
void sgemm_nt(const float* __restrict__ A, const float* __restrict__ B,
              float* __restrict__ C,
              int M, int N, int Klen, int lda, int ldb, int ldc) {
    __shared__ float As[KB][TILE + 4];
    __shared__ float Bs[KB][TILE + 4];

    const int m0 = blockIdx.y * TILE;
    const int n0 = blockIdx.x * TILE;
    const int tid = threadIdx.x;
    const int tx = tid & 15;
    const int ty = tid >> 4;

    float acc[8][8];
#pragma unroll
    for (int i = 0; i < 8; i++)
#pragma unroll
        for (int j = 0; j < 8; j++) acc[i][j] = 0.f;

    for (int kk = 0; kk < Klen; kk += KB) {
#pragma unroll
        for (int i = 0; i < (TILE * KB) / 256; i++) {
            int idx = tid + i * 256;
            int k = idx % KB;
            int m = idx / KB;
            int gm = m0 + m;
            float v = 0.f;
            if (gm < M) v = A[(long long)gm * lda + (kk + k)];
            As[k][m] = v;
        }
#pragma unroll
        for (int i = 0; i < (TILE * KB) / 256; i++) {
            int idx = tid + i * 256;
            int k = idx % KB;
            int n = idx / KB;
            int gn = n0 + n;
            float v = 0.f;
            if (gn < N) v = B[(long long)gn * ldb + (kk + k)];
            Bs[k][n] = v;
        }
        __syncthreads();

#pragma unroll
        for (int kb = 0; kb < KB; kb++) {
            float af[8], bf[8];
#pragma unroll
            for (int i = 0; i < 8; i++) af[i] = As[kb][ty * 8 + i];
#pragma unroll
            for (int j = 0; j < 8; j++) bf[j] = Bs[kb][tx * 8 + j];
#pragma unroll
            for (int i = 0; i < 8; i++)
#pragma unroll
                for (int j = 0; j < 8; j++)
                    acc[i][j] = fmaf(af[i], bf[j], acc[i][j]);
        }
        __syncthreads();
    }

#pragma unroll
    for (int i = 0; i < 8; i++) {
        int gm = m0 + ty * 8 + i;
        if (gm < M) {
#pragma unroll
            for (int j = 0; j < 8; j++) {
                int gn = n0 + tx * 8 + j;
                if (gn < N) C[(long long)gm * ldc + gn] = acc[i][j];
            }
        }
    }
}

// ---------------- device-wide barrier (all NCTA CTAs co-resident) ------------
__device__ __forceinline__ void grid_barrier(unsigned int gen) {
    __syncthreads();
    if (threadIdx.x == 0) {
        __threadfence();
        unsigned int a = atomicAdd(&g_barcnt, 1u);
        if (a == NCTA - 1) {
            atomicExch(&g_barcnt, 0u);
            __threadfence();
            atomicExch(&g_bargen, gen);
        } else {
            for (;;) {
                unsigned int v;
                asm volatile("ld.global.acquire.gpu.u32 %0, [%1];"
                             : "=r"(v) : "l"(&g_bargen));
                if (v >= gen) break;
                __nanosleep(64);
            }
        }
    }
    __syncthreads();
}

// ---------------- fused LSTM cell update for one (b,u) cell ------------------
__device__ __forceinline__ void cell_update(
    int cell, int t, int b0c, int u0,
    const float* __restrict__ gp,
    const float* __restrict__ P,
    const int* __restrict__ ids,
    const float* __restrict__ bsum,   // 4 hoisted bias values for this cell
    float* __restrict__ hout,
    float& creg, float& hsreg)
{
    int bl = cell / UT;
    int du = cell - bl * UT;
    int u  = u0 + du;
    int gb = b0c + bl;

    float g4[4];
#pragma unroll
    for (int g = 0; g < 4; g++) {
        float s = bsum[g];
#pragma unroll
        for (int z = 0; z < KZ; z++)
            s += gp[z * (BT * RT) + bl * RT + g * UT + du];
        g4[g] = s;
    }
    if (t != T_SZ - 1) {   // emb[T-1] zeroed by reference's negative-index quirk
        int idA = ids[gb * T_SZ + t];
        const float* PA = P + (long long)idA * PCOLS;
#pragma unroll
        for (int g = 0; g < 4; g++) g4[g] += PA[g * HID + u];
    }
    if (t != 0) {          // emb_{-1} is zero padding
        int idB = ids[gb * T_SZ + t - 1];
        const float* PB = P + (long long)idB * PCOLS + GATES;
#pragma unroll
        for (int g = 0; g < 4; g++) g4[g] += PB[g * HID + u];
    }

    float ig = 1.f / (1.f + expf(-g4[0]));
    float fg = 1.f / (1.f + expf(-g4[1]));
    float gg = tanhf(g4[2]);
    float og = 1.f / (1.f + expf(-g4[3]));

    creg = fg * creg + ig * gg;
    float hv = og * tanhf(creg);
    hout[gb * HID + u] = hv;
    hsreg += hv;
}

// ---------------- persistent recurrence kernel --------------------------------
// grid = 120 CTAs (8 b-tiles x 15 u-tiles), 256 threads.
// smem: Wt[300][84] (this CTA's 80 W_hh rows, k-major, loaded once)
//       hsm[32][301] (h tile for this step)
//       gp[4][32*80]  (K-split partial gates)
#define SM_WT   (300 * 84)
#define SM_H    (BT * 301)
#define SM_GP   (KZ * BT * RT)
#define SM_FLOATS (SM_WT + SM_H + SM_GP)

__global__ __launch_bounds__(256, 1)
void lstm_persistent(const float* __restrict__ W_hh,
                     const float* __restrict__ P,
                     const int* __restrict__ ids,
                     const float* __restrict__ b_ih,
                     const float* __restrict__ b_hh,
                     float* __restrict__ hbuf,
                     float* __restrict__ hsum) {
    extern __shared__ float sm[];
    float* Wt  = sm;                  // [k][r], stride 84
    float* hsm = sm + SM_WT;          // [b][k], stride 301
    float* gp  = sm + SM_WT + SM_H;   // [kz][b*80+r]

    const int tid = threadIdx.x;
    const int bt  = blockIdx.x & 7;        // 0..7
    const int ut  = blockIdx.x >> 3;       // 0..14
    const int b0c = bt * BT;
    const int u0  = ut * UT;

    // ---- load this CTA's W_hh rows into smem (once), k-major ----
    for (int idx = tid; idx < RT * HID; idx += 256) {
        int r = idx / HID;
        int k = idx - r * HID;
        int g = r / UT;
        int du = r - g * UT;
        Wt[k * 84 + r] = W_hh[(g * HID + u0 + du) * HID + k];
    }

    // ---- compute-phase thread mapping ----
    const int kz   = tid >> 6;             // 0..3
    const int w    = tid & 63;
    const int tb0  = (w >> 4) * 8;         // 0,8,16,24
    const int tr0  = (w & 15) * 5;         // 0..75
    const int kbeg = kz * KC;

    // ---- pointwise-phase fixed cell ownership (c, hsum live in registers) ----
    const int cell0 = tid;                 // < 640
    const int cell1 = tid + 256;           // < 640
    const int cell2 = tid + 512;           // valid iff tid < 128
    float creg0 = 0.f, creg1 = 0.f, creg2 = 0.f;
    float hs0 = 0.f, hs1 = 0.f, hs2 = 0.f;

    // hoist bias sums (b_ih + b_hh) per owned cell
    float bs0[4], bs1[4], bs2[4];
    {
        int u_0 = u0 + (cell0 % UT);
        int u_1 = u0 + (cell1 % UT);
        int u_2 = u0 + (cell2 % UT);
#pragma unroll
        for (int g = 0; g < 4; g++) {
            bs0[g] = b_ih[g * HID + u_0] + b_hh[g * HID + u_0];
            bs1[g] = b_ih[g * HID + u_1] + b_hh[g * HID + u_1];
            bs2[g] = (tid < 128) ? (b_ih[g * HID + u_2] + b_hh[g * HID + u_2]) : 0.f;
        }
    }

    __syncthreads();

    unsigned int gen = 0;
    for (int t = 0; t < T_SZ; t++) {
        const float* hin  = hbuf + (t & 1) * (B_SZ * HID);
        float*       hout = hbuf + ((t + 1) & 1) * (B_SZ * HID);

        // ---- stage h tile [32 x 300] (coalesced LDG, conflict-free STS) ----
        {
            int b = 0, k = tid;                    // tid < 300 always
            for (int idx = tid; idx < BT * HID; idx += 256) {
                hsm[b * 301 + k] = hin[(b0c + b) * HID + k];
                k += 256;
                if (k >= HID) { k -= HID; b++; }
            }
        }
        __syncthreads();

        // ---- gates GEMM: 32x80 outputs, full K via 4-way split ----
        float acc[8][5];
#pragma unroll
        for (int i = 0; i < 8; i++)
#pragma unroll
            for (int j = 0; j < 5; j++) acc[i][j] = 0.f;

        for (int k2 = kbeg; k2 < kbeg + KC; k2++) {
            float hv[8], wv[5];
#pragma unroll
            for (int i = 0; i < 8; i++) hv[i] = hsm[(tb0 + i) * 301 + k2];
#pragma unroll
            for (int j = 0; j < 5; j++) wv[j] = Wt[k2 * 84 + tr0 + j];
#pragma unroll
            for (int i = 0; i < 8; i++)
#pragma unroll
                for (int j = 0; j < 5; j++)
                    acc[i][j] = fmaf(hv[i], wv[j], acc[i][j]);
        }

#pragma unroll
        for (int i = 0; i < 8; i++)
#pragma unroll
            for (int j = 0; j < 5; j++)
                gp[kz * (BT * RT) + (tb0 + i) * RT + tr0 + j] = acc[i][j];
        __syncthreads();

        // ---- fused cell update (reduce K-splits + P gathers + activations) ----
        cell_update(cell0, t, b0c, u0, gp, P, ids, bs0, hout, creg0, hs0);
        cell_update(cell1, t, b0c, u0, gp, P, ids, bs1, hout, creg1, hs1);
        if (tid < 128)
            cell_update(cell2, t, b0c, u0, gp, P, ids, bs2, hout, creg2, hs2);

        // ---- all CTAs must finish step t before anyone starts t+1 ----
        gen++;
        grid_barrier(gen);
    }

    // ---- write out hidden-state sums for the classifier ----
    {
        int bl = cell0 / UT, du = cell0 - bl * UT;
        hsum[(b0c + bl) * HID + u0 + du] = hs0;
        bl = cell1 / UT; du = cell1 - bl * UT;
        hsum[(b0c + bl) * HID + u0 + du] = hs1;
        if (tid < 128) {
            bl = cell2 / UT; du = cell2 - bl * UT;
            hsum[(b0c + bl) * HID + u0 + du] = hs2;
        }
    }
}

// ---------------- classifier head: mean-pool -> dense(100) -> dense(5) -> LSM
__global__ void classifier(const float* __restrict__ hsum,
                           const float* __restrict__ W1, const float* __restrict__ b1,
                           const float* __restrict__ W2, const float* __restrict__ b2,
                           float* __restrict__ out) {
    int b = blockIdx.x;
    int tid = threadIdx.x;   // 128
    __shared__ float pooled[HID];
    __shared__ float l1s[100];
    __shared__ float l2s[NCLS];

    for (int i = tid; i < HID; i += blockDim.x)
        pooled[i] = hsum[b * HID + i] * (1.f / (float)T_SZ);
    __syncthreads();

    if (tid < 100) {
        float s = b1[tid];
        const float* wr = W1 + tid * HID;
#pragma unroll 4
        for (int k = 0; k < HID; k++) s = fmaf(pooled[k], wr[k], s);
        l1s[tid] = 1.f / (1.f + expf(-s));
    }
    __syncthreads();

    if (tid < NCLS) {
        float s = b2[tid];
        const float* wr = W2 + tid * 100;
#pragma unroll 4
        for (int k = 0; k < 100; k++) s = fmaf(l1s[k], wr[k], s);
        l2s[tid] = 1.f / (1.f + expf(-s));
    }
    __syncthreads();

    if (tid < NCLS) {
        float m = l2s[0];
#pragma unroll
        for (int j = 1; j < NCLS; j++) m = fmaxf(m, l2s[j]);
        float sum = 0.f;
#pragma unroll
        for (int j = 0; j < NCLS; j++) sum += expf(l2s[j] - m);
        out[b * NCLS + tid] = l2s[tid] - m - logf(sum);
    }
}

// ------------------------------ launch ---------------------------------------
extern "C" void kernel_launch(void* const* d_in, const int* in_sizes, int n_in,
                              void* d_out, int out_size) {
    const int*   ids  = nullptr;
    const float* glove = nullptr, *W_ih = nullptr, *W_hh = nullptr;
    const float* b_ih = nullptr, *b_hh = nullptr;
    const float* W1 = nullptr, *b1 = nullptr, *W2 = nullptr, *b2 = nullptr;

    for (int i = 0; i < n_in; i++) {
        switch (in_sizes[i]) {
            case B_SZ * T_SZ:      ids   = (const int*)d_in[i];   break;
            case VOCAB * EMB:      glove = (const float*)d_in[i]; break;
            case GATES * 600:      W_ih  = (const float*)d_in[i]; break;
            case GATES * HID:      W_hh  = (const float*)d_in[i]; break;
            case GATES:            if (!b_ih) b_ih = (const float*)d_in[i];
                                   else       b_hh = (const float*)d_in[i]; break;
            case 100 * HID:        W1 = (const float*)d_in[i]; break;
            case 100:              b1 = (const float*)d_in[i]; break;
            case NCLS * 100:       W2 = (const float*)d_in[i]; break;
            case NCLS:             b2 = (const float*)d_in[i]; break;
            default: break; // size-1 scalar (max_num_of_words) ignored
        }
    }
    if (!ids || !glove || !W_ih || !W_hh || !b_ih || !b_hh || !W1 || !b1 || !W2 || !b2)
        return;

    float *P, *Wcat, *hbuf, *hsum;
    cudaGetSymbolAddress((void**)&P,    d_P);
    cudaGetSymbolAddress((void**)&Wcat, d_Wcat);
    cudaGetSymbolAddress((void**)&hbuf, d_h);
    cudaGetSymbolAddress((void**)&hsum, d_hsum);

    // one-time attribute set for the big dynamic smem (idempotent, not an alloc)
    static bool attr_done = false;
    if (!attr_done) {
        cudaFuncSetAttribute(lstm_persistent,
                             cudaFuncAttributeMaxDynamicSharedMemorySize,
                             SM_FLOATS * (int)sizeof(float));
        attr_done = true;
    }

    // 1) repack W_ih, zero h0, reset barrier     [1 node]
    prep_kernel<<<(PCOLS * EMB + 255) / 256, 256>>>(W_ih, Wcat, hbuf);

    // 2) vocabulary projection P = glove @ Wcat^T [1 node]
    {
        dim3 grid((PCOLS + TILE - 1) / TILE, (VOCAB + TILE - 1) / TILE, 1);
        sgemm_nt<<<grid, 256>>>(glove, Wcat, P,
                                VOCAB, PCOLS, EMB, EMB, EMB, PCOLS);
    }

    // 3) whole 512-step LSTM in one persistent kernel [1 node]
    lstm_persistent<<<NCTA, 256, SM_FLOATS * sizeof(float)>>>(
        W_hh, P, ids, b_ih, b_hh, hbuf, hsum);

    // 4) classifier head [1 node]
    classifier<<<B_SZ, 128>>>(hsum, W1, b1, W2, b2, (float*)d_out);
}

// round 6
// speedup vs baseline: 1.2652x; 1.2652x over previous
#include <cuda_runtime.h>
#include <cuda_bf16.h>
#include <math.h>

// ---------------- problem constants ----------------
#define B_SZ   256
#define T_SZ   512
#define HID    300
#define EMB    300
#define VOCAB  50000
#define NCLS   5
#define GATES  1200        // 4*HID
#define PCOLS  2400        // 2*GATES (A-part | B-part)

// recurrence persistent-kernel tiling
#define NCTA   120         // 8 b-tiles x 15 u-tiles (<= 148 SMs, 1 CTA/SM)
#define BT     32          // batch rows per CTA
#define UT     20          // hidden units per CTA
#define RT     80          // 4 gates * UT rows per CTA
#define KZ     4           // internal K split (one warp each)
#define KC     75          // K chunk (4*75 = 300)
#define GPS    88          // gp row stride (conflict-free STS.64, see analysis)

typedef unsigned long long u64;

// ---------------- f32x2 packed-FMA helpers (exact fp32 FMA semantics) --------
__device__ __forceinline__ void ffma2(u64& d, u64 a, u64 b) {
    asm("fma.rn.f32x2 %0, %1, %2, %0;" : "+l"(d) : "l"(a), "l"(b));
}
__device__ __forceinline__ u64 dup2(float x) {
    u64 r; asm("mov.b64 %0, {%1, %1};" : "=l"(r) : "f"(x)); return r;
}
__device__ __forceinline__ float2 unpack2(u64 v) {
    float2 f; asm("mov.b64 {%0, %1}, %2;" : "=f"(f.x), "=f"(f.y) : "l"(v)); return f;
}

// ---------------- static device scratch (no allocations allowed) -------------
__device__ float d_P[(long long)VOCAB * PCOLS];     // 480 MB: glove @ [A|B]^T
__device__ float d_Wcat[PCOLS * EMB];               // repacked W_ih
__device__ float d_h[2 * B_SZ * HID];               // double-buffered h
__device__ float d_hsum[B_SZ * HID];                // sum_t h_t
__device__ unsigned int d_arrive[NCTA];
__device__ unsigned int d_go;

// ---------------- prep: repack W_ih, zero h0, reset barrier flags ------------
__global__ void prep_kernel(const float* __restrict__ W_ih,
                            float* __restrict__ Wcat,
                            float* __restrict__ h0) {
    int i = blockIdx.x * blockDim.x + threadIdx.x;
    if (i < PCOLS * EMB) {
        int n = i / EMB, k = i % EMB;
        Wcat[i] = (n < GATES) ? W_ih[n * 600 + k]
                              : W_ih[(n - GATES) * 600 + 300 + k];
    }
    if (i < B_SZ * HID) h0[i] = 0.f;
    if (i < NCTA) d_arrive[i] = 0u;
    if (i == 0) d_go = 0u;
}

// ---------------- C = A @ B^T with packed f32x2 FMA ---------------------------
// 128x128 tile, 256 threads. Thread output columns: pairs at n0 + 2*tx + 32*p
// (conflict-free LDS.64 on B fragments: 16 lanes x 8B cover all 32 banks).
#define TILE 128
#define KB   10
__global__ __launch_bounds__(256)
void sgemm_f2(const float* __restrict__ A, const float* __restrict__ B,
              float* __restrict__ C,
              int M, int N, int Klen, int lda, int ldb, int ldc) {
    __shared__ __align__(16) float As[KB][TILE + 4];
    __shared__ __align__(16) float Bs[KB][TILE + 4];

    const int m0 = blockIdx.y * TILE;
    const int n0 = blockIdx.x * TILE;
    const int tid = threadIdx.x;
    const int tx = tid & 15;     // 16 col-groups
    const int ty = tid >> 4;     // 16 row-groups of 8

    u64 acc[8][4];
#pragma unroll
    for (int i = 0; i < 8; i++)
#pragma unroll
        for (int p = 0; p < 4; p++) acc[i][p] = 0ULL;

    for (int kk = 0; kk < Klen; kk += KB) {
#pragma unroll
        for (int it = 0; it < (TILE * KB) / 256; it++) {
            int idx = tid + it * 256;
            int k = idx % KB;
            int m = idx / KB;
            int gm = m0 + m;
            float v = 0.f;
            if (gm < M) v = A[(long long)gm * lda + (kk + k)];
            As[k][m] = v;
        }
#pragma unroll
        for (int it = 0; it < (TILE * KB) / 256; it++) {
            int idx = tid + it * 256;
            int k = idx % KB;
            int n = idx / KB;
            int gn = n0 + n;
            float v = 0.f;
            if (gn < N) v = B[(long long)gn * ldb + (kk + k)];
            Bs[k][n] = v;
        }
        __syncthreads();

#pragma unroll
        for (int kb = 0; kb < KB; kb++) {
            u64 ad[8], bd[4];
#pragma unroll
            for (int i = 0; i < 8; i++) ad[i] = dup2(As[kb][ty * 8 + i]);
#pragma unroll
            for (int p = 0; p < 4; p++)
                bd[p] = *(const u64*)&Bs[kb][2 * tx + 32 * p];
#pragma unroll
            for (int i = 0; i < 8; i++)
#pragma unroll
                for (int p = 0; p < 4; p++)
                    ffma2(acc[i][p], ad[i], bd[p]);
        }
        __syncthreads();
    }

#pragma unroll
    for (int i = 0; i < 8; i++) {
        int gm = m0 + ty * 8 + i;
        if (gm < M) {
#pragma unroll
            for (int p = 0; p < 4; p++) {
                int gn = n0 + 2 * tx + 32 * p;
                if (gn < N)   // N even, gn even -> pair in-bounds
                    *(u64*)&C[(long long)gm * ldc + gn] = acc[i][p];
            }
        }
    }
}

// ---------------- flag-based grid barrier (all NCTA CTAs co-resident) --------
__device__ __forceinline__ unsigned int ld_acq(const unsigned int* p) {
    unsigned int v;
    asm volatile("ld.global.acquire.gpu.u32 %0, [%1];" : "=r"(v) : "l"(p));
    return v;
}
__device__ __forceinline__ void st_rel(unsigned int* p, unsigned int v) {
    asm volatile("st.global.release.gpu.u32 [%0], %1;" :: "l"(p), "r"(v));
}
__device__ __forceinline__ void grid_barrier(unsigned int gen) {
    __syncthreads();
    if (blockIdx.x == 0) {
        // CTA0: threads 1..NCTA-1 each poll one arrival flag, then release
        if (threadIdx.x > 0 && threadIdx.x < NCTA) {
            while (ld_acq(&d_arrive[threadIdx.x]) < gen) {}
        }
        __syncthreads();
        if (threadIdx.x == 0) st_rel(&d_go, gen);
    } else {
        if (threadIdx.x == 0) {
            st_rel(&d_arrive[blockIdx.x], gen);
            while (ld_acq(&d_go) < gen) {}
        }
        __syncthreads();
    }
}

// ---------------- persistent recurrence kernel --------------------------------
// 120 CTAs x 256 threads. GEMM phase: threads 0..127 = 4 warps, one K-split
// each (warp w on SMSP w), 8x10 cells/thread with f32x2 FMA.
// smem: Wt[300][84] (W_hh rows k-major, loaded once)
//       hsm[32][301] (h tile, b-major)
//       gp[4][32][88] (K-split partials; stride 88 + b=tx+4i => conflict-free)
#define SM_WT   (300 * 84)            // 25200
#define SM_H    (BT * 301)            // 9632
#define SM_GP   (KZ * BT * GPS)       // 11264
#define SM_FLOATS (SM_WT + SM_H + SM_GP)

__global__ __launch_bounds__(256, 1)
void lstm_persistent(const float* __restrict__ W_hh,
                     const float* __restrict__ P,
                     const int* __restrict__ ids,
                     const float* __restrict__ b_ih,
                     const float* __restrict__ b_hh,
                     float* __restrict__ hbuf,
                     float* __restrict__ hsum) {
    extern __shared__ __align__(16) float sm[];
    float* Wt  = sm;                  // [k][r], stride 84
    float* hsm = sm + SM_WT;          // [b][k], stride 301
    float* gp  = sm + SM_WT + SM_H;   // [kz][b][r], b-stride 88

    const int tid = threadIdx.x;
    const int bt  = blockIdx.x & 7;        // 0..7
    const int ut  = blockIdx.x >> 3;       // 0..14
    const int b0c = bt * BT;
    const int u0  = ut * UT;

    // ---- load this CTA's 80 W_hh rows into smem (once), k-major ----
    for (int idx = tid; idx < RT * HID; idx += 256) {
        int r = idx / HID;
        int k = idx - r * HID;
        int g = r / UT;
        int du = r - g * UT;
        Wt[k * 84 + r] = W_hh[(g * HID + u0 + du) * HID + k];
    }

    // ---- GEMM-phase mapping (threads 0..127) ----
    const int lane = tid & 31;
    const int wrp  = tid >> 5;             // warp id; == kz for warps 0..3
    const int gtx  = lane & 3;             // b-group: b = gtx + 4*i
    const int gty  = lane >> 2;            // r-group: r = gty*10 + {0..9}
    const int kbeg = wrp * KC;

    // ---- pointwise-phase fixed cell ownership (c, hsum in registers) ----
    int bl[3], du[3];
#pragma unroll
    for (int c = 0; c < 3; c++) {
        int cell = tid + c * 256;          // cell2 valid iff tid < 128
        bl[c] = cell / UT;
        du[c] = cell - bl[c] * UT;
    }
    float cr[3] = {0.f, 0.f, 0.f};
    float hs[3] = {0.f, 0.f, 0.f};
    float bs[3][4];
#pragma unroll
    for (int c = 0; c < 3; c++) {
        bool act = (c < 2) || (tid < 128);
#pragma unroll
        for (int g = 0; g < 4; g++) {
            int col = g * HID + u0 + du[c];
            bs[c][g] = act ? (b_ih[col] + b_hh[col]) : 0.f;
        }
    }

    __syncthreads();

    for (int t = 0; t < T_SZ; t++) {
        const float* hin  = hbuf + (t & 1) * (B_SZ * HID);
        float*       hout = hbuf + ((t + 1) & 1) * (B_SZ * HID);

        // ---- stage h tile [32 x 300] (coalesced LDG, conflict-free STS) ----
        for (int idx = tid; idx < BT * HID; idx += 256) {
            int b = idx / HID;
            int k = idx - b * HID;
            hsm[b * 301 + k] = hin[(b0c + b) * HID + k];
        }
        __syncthreads();

        // ---- gates GEMM: 32x80 outputs, 4 warp-K-splits, f32x2 FMA ----
        if (tid < 128) {
            u64 acc[8][5];
#pragma unroll
            for (int i = 0; i < 8; i++)
#pragma unroll
                for (int q = 0; q < 5; q++) acc[i][q] = 0ULL;

#pragma unroll 3
            for (int k = kbeg; k < kbeg + KC; k++) {
                u64 hd[8], wd[5];
#pragma unroll
                for (int i = 0; i < 8; i++)
                    hd[i] = dup2(hsm[(gtx + 4 * i) * 301 + k]);
#pragma unroll
                for (int q = 0; q < 5; q++)
                    wd[q] = *(const u64*)&Wt[k * 84 + gty * 10 + 2 * q];
#pragma unroll
                for (int i = 0; i < 8; i++)
#pragma unroll
                    for (int q = 0; q < 5; q++)
                        ffma2(acc[i][q], hd[i], wd[q]);
            }
#pragma unroll
            for (int i = 0; i < 8; i++)
#pragma unroll
                for (int q = 0; q < 5; q++)
                    *(u64*)&gp[wrp * (BT * GPS) + (gtx + 4 * i) * GPS +
                               gty * 10 + 2 * q] = acc[i][q];
        }
        __syncthreads();

        // ---- fused cell update: gather all loads first (max MLP), then act --
        float g4[3][4];
#pragma unroll
        for (int c = 0; c < 3; c++) {
            bool act = (c < 2) || (tid < 128);
            if (act) {
#pragma unroll
                for (int g = 0; g < 4; g++) {
                    float s = bs[c][g];
#pragma unroll
                    for (int z = 0; z < KZ; z++)
                        s += gp[z * (BT * GPS) + bl[c] * GPS + g * UT + du[c]];
                    g4[c][g] = s;
                }
                if (t != T_SZ - 1) {  // emb[T-1] zeroed (reference quirk)
                    int idA = ids[(b0c + bl[c]) * T_SZ + t];
                    const float* PA = P + (long long)idA * PCOLS;
#pragma unroll
                    for (int g = 0; g < 4; g++)
                        g4[c][g] += PA[g * HID + u0 + du[c]];
                }
                if (t != 0) {         // emb_{-1} is zero padding
                    int idB = ids[(b0c + bl[c]) * T_SZ + t - 1];
                    const float* PB = P + (long long)idB * PCOLS + GATES;
#pragma unroll
                    for (int g = 0; g < 4; g++)
                        g4[c][g] += PB[g * HID + u0 + du[c]];
                }
            }
        }
#pragma unroll
        for (int c = 0; c < 3; c++) {
            bool act = (c < 2) || (tid < 128);
            if (act) {
                float ig = 1.f / (1.f + expf(-g4[c][0]));
                float fg = 1.f / (1.f + expf(-g4[c][1]));
                float gg = tanhf(g4[c][2]);
                float og = 1.f / (1.f + expf(-g4[c][3]));
                cr[c] = fg * cr[c] + ig * gg;
                float hv = og * tanhf(cr[c]);
                hout[(b0c + bl[c]) * HID + u0 + du[c]] = hv;
                hs[c] += hv;
            }
        }

        // ---- all CTAs must finish step t before anyone starts t+1 ----
        grid_barrier((unsigned int)(t + 1));
    }

    // ---- write hidden-state sums for the classifier ----
#pragma unroll
    for (int c = 0; c < 3; c++) {
        bool act = (c < 2) || (tid < 128);
        if (act)
            hsum[(b0c + bl[c]) * HID + u0 + du[c]] = hs[c];
    }
}

// ---------------- classifier head: mean-pool -> dense(100) -> dense(5) -> LSM
__global__ void classifier(const float* __restrict__ hsum,
                           const float* __restrict__ W1, const float* __restrict__ b1,
                           const float* __restrict__ W2, const float* __restrict__ b2,
                           float* __restrict__ out) {
    int b = blockIdx.x;
    int tid = threadIdx.x;   // 128
    __shared__ float pooled[HID];
    __shared__ float l1s[100];
    __shared__ float l2s[NCLS];

    for (int i = tid; i < HID; i += blockDim.x)
        pooled[i] = hsum[b * HID + i] * (1.f / (float)T_SZ);
    __syncthreads();

    if (tid < 100) {
        float s = b1[tid];
        const float* wr = W1 + tid * HID;
#pragma unroll 4
        for (int k = 0; k < HID; k++) s = fmaf(pooled[k], wr[k], s);
        l1s[tid] = 1.f / (1.f + expf(-s));
    }
    __syncthreads();

    if (tid < NCLS) {
        float s = b2[tid];
        const float* wr = W2 + tid * 100;
#pragma unroll 4
        for (int k = 0; k < 100; k++) s = fmaf(l1s[k], wr[k], s);
        l2s[tid] = 1.f / (1.f + expf(-s));
    }
    __syncthreads();

    if (tid < NCLS) {
        float m = l2s[0];
#pragma unroll
        for (int j = 1; j < NCLS; j++) m = fmaxf(m, l2s[j]);
        float sum = 0.f;
#pragma unroll
        for (int j = 0; j < NCLS; j++) sum += expf(l2s[j] - m);
        out[b * NCLS + tid] = l2s[tid] - m - logf(sum);
    }
}

// ------------------------------ launch ---------------------------------------
extern "C" void kernel_launch(void* const* d_in, const int* in_sizes, int n_in,
                              void* d_out, int out_size) {
    const int*   ids  = nullptr;
    const float* glove = nullptr, *W_ih = nullptr, *W_hh = nullptr;
    const float* b_ih = nullptr, *b_hh = nullptr;
    const float* W1 = nullptr, *b1 = nullptr, *W2 = nullptr, *b2 = nullptr;

    for (int i = 0; i < n_in; i++) {
        switch (in_sizes[i]) {
            case B_SZ * T_SZ:      ids   = (const int*)d_in[i];   break;
            case VOCAB * EMB:      glove = (const float*)d_in[i]; break;
            case GATES * 600:      W_ih  = (const float*)d_in[i]; break;
            case GATES * HID:      W_hh  = (const float*)d_in[i]; break;
            case GATES:            if (!b_ih) b_ih = (const float*)d_in[i];
                                   else       b_hh = (const float*)d_in[i]; break;
            case 100 * HID:        W1 = (const float*)d_in[i]; break;
            case 100:              b1 = (const float*)d_in[i]; break;
            case NCLS * 100:       W2 = (const float*)d_in[i]; break;
            case NCLS:             b2 = (const float*)d_in[i]; break;
            default: break; // size-1 scalar (max_num_of_words) ignored
        }
    }
    if (!ids || !glove || !W_ih || !W_hh || !b_ih || !b_hh || !W1 || !b1 || !W2 || !b2)
        return;

    float *P, *Wcat, *hbuf, *hsum;
    cudaGetSymbolAddress((void**)&P,    d_P);
    cudaGetSymbolAddress((void**)&Wcat, d_Wcat);
    cudaGetSymbolAddress((void**)&hbuf, d_h);
    cudaGetSymbolAddress((void**)&hsum, d_hsum);

    static bool attr_done = false;
    if (!attr_done) {
        cudaFuncSetAttribute(lstm_persistent,
                             cudaFuncAttributeMaxDynamicSharedMemorySize,
                             SM_FLOATS * (int)sizeof(float));
        attr_done = true;
    }

    // 1) repack W_ih, zero h0 + barrier flags       [1 node]
    prep_kernel<<<(PCOLS * EMB + 255) / 256, 256>>>(W_ih, Wcat, hbuf);

    // 2) vocabulary projection P = glove @ Wcat^T   [1 node]
    {
        dim3 grid((PCOLS + TILE - 1) / TILE, (VOCAB + TILE - 1) / TILE, 1);
        sgemm_f2<<<grid, 256>>>(glove, Wcat, P,
                                VOCAB, PCOLS, EMB, EMB, EMB, PCOLS);
    }

    // 3) whole 512-step LSTM in one persistent kernel [1 node]
    lstm_persistent<<<NCTA, 256, SM_FLOATS * sizeof(float)>>>(
        W_hh, P, ids, b_ih, b_hh, hbuf, hsum);

    // 4) classifier head [1 node]
    classifier<<<B_SZ, 128>>>(hsum, W1, b1, W2, b2, (float*)d_out);
}

// round 7
// speedup vs baseline: 1.9254x; 1.5219x over previous
#include <cuda_runtime.h>
#include <cuda_bf16.h>
#include <math.h>

// ---------------- problem constants ----------------
#define B_SZ   256
#define T_SZ   512
#define HID    300
#define EMB    300
#define VOCAB  50000
#define NCLS   5
#define GATES  1200        // 4*HID
#define PCOLS  2400        // 2*GATES (A-part | B-part)

// recurrence persistent-kernel tiling
#define NCTA   120         // 8 bt-groups x 15 u-tiles (1 CTA/SM, all resident)
#define BT     32          // batch rows per CTA
#define UT     20          // hidden units per CTA
#define RT     80          // 4 gates * UT rows per CTA
#define KZ     4           // K splits (75 each); 2 warps per split (b-halves)
#define KC     75
#define GPS    88          // gp row stride

typedef unsigned long long u64;
typedef unsigned int u32;

// ---------------- f32x2 packed-FMA helpers (exact fp32 FMA semantics) --------
__device__ __forceinline__ void ffma2(u64& d, u64 a, u64 b) {
    asm("fma.rn.f32x2 %0, %1, %2, %0;" : "+l"(d) : "l"(a), "l"(b));
}
__device__ __forceinline__ u64 dup2(float x) {
    u64 r; asm("mov.b64 %0, {%1, %1};" : "=l"(r) : "f"(x)); return r;
}

// ---------------- fast activations (MUFU-based, rel err ~1e-6) ---------------
__device__ __forceinline__ float fsig(float x) {
    return __fdividef(1.f, 1.f + __expf(-x));   // saturates correctly at +/-inf
}

// ---------------- static device scratch (no allocations allowed) -------------
__device__ float d_P[(long long)VOCAB * PCOLS];      // 480 MB: glove @ [A|B]^T
__device__ float d_Wcat[PCOLS * EMB];                // repacked W_ih
__device__ __align__(256) float d_h[2 * B_SZ * HID]; // double-buffered h
__device__ float d_hsum[B_SZ * HID];                 // sum_t h_t
__device__ unsigned int d_arrive[8][16];             // per-bt-group flags

// ---------------- prep: repack W_ih, zero h0, reset barrier flags ------------
__global__ void prep_kernel(const float* __restrict__ W_ih,
                            float* __restrict__ Wcat,
                            float* __restrict__ h0) {
    int i = blockIdx.x * blockDim.x + threadIdx.x;
    if (i < PCOLS * EMB) {
        int n = i / EMB, k = i % EMB;
        Wcat[i] = (n < GATES) ? W_ih[n * 600 + k]
                              : W_ih[(n - GATES) * 600 + 300 + k];
    }
    if (i < B_SZ * HID) h0[i] = 0.f;
    if (i < 128) ((unsigned int*)d_arrive)[i] = 0u;
}

// ---------------- C = A @ B^T with packed f32x2 FMA (verified R5 kernel) -----
#define TILE 128
#define KB   10
__global__ __launch_bounds__(256)
void sgemm_f2(const float* __restrict__ A, const float* __restrict__ B,
              float* __restrict__ C,
              int M, int N, int Klen, int lda, int ldb, int ldc) {
    __shared__ __align__(16) float As[KB][TILE + 4];
    __shared__ __align__(16) float Bs[KB][TILE + 4];

    const int m0 = blockIdx.y * TILE;
    const int n0 = blockIdx.x * TILE;
    const int tid = threadIdx.x;
    const int tx = tid & 15;
    const int ty = tid >> 4;

    u64 acc[8][4];
#pragma unroll
    for (int i = 0; i < 8; i++)
#pragma unroll
        for (int p = 0; p < 4; p++) acc[i][p] = 0ULL;

    for (int kk = 0; kk < Klen; kk += KB) {
#pragma unroll
        for (int it = 0; it < (TILE * KB) / 256; it++) {
            int idx = tid + it * 256;
            int k = idx % KB;
            int m = idx / KB;
            int gm = m0 + m;
            float v = 0.f;
            if (gm < M) v = A[(long long)gm * lda + (kk + k)];
            As[k][m] = v;
        }
#pragma unroll
        for (int it = 0; it < (TILE * KB) / 256; it++) {
            int idx = tid + it * 256;
            int k = idx % KB;
            int n = idx / KB;
            int gn = n0 + n;
            float v = 0.f;
            if (gn < N) v = B[(long long)gn * ldb + (kk + k)];
            Bs[k][n] = v;
        }
        __syncthreads();

#pragma unroll
        for (int kb = 0; kb < KB; kb++) {
            u64 ad[8], bd[4];
#pragma unroll
            for (int i = 0; i < 8; i++) ad[i] = dup2(As[kb][ty * 8 + i]);
#pragma unroll
            for (int p = 0; p < 4; p++)
                bd[p] = *(const u64*)&Bs[kb][2 * tx + 32 * p];
#pragma unroll
            for (int i = 0; i < 8; i++)
#pragma unroll
                for (int p = 0; p < 4; p++)
                    ffma2(acc[i][p], ad[i], bd[p]);
        }
        __syncthreads();
    }

#pragma unroll
    for (int i = 0; i < 8; i++) {
        int gm = m0 + ty * 8 + i;
        if (gm < M) {
#pragma unroll
            for (int p = 0; p < 4; p++) {
                int gn = n0 + 2 * tx + 32 * p;
                if (gn < N)
                    *(u64*)&C[(long long)gm * ldc + gn] = acc[i][p];
            }
        }
    }
}

// ---------------- acquire/release helpers ------------------------------------
__device__ __forceinline__ unsigned int ld_acq(const unsigned int* p) {
    unsigned int v;
    asm volatile("ld.global.acquire.gpu.u32 %0, [%1];" : "=r"(v) : "l"(p));
    return v;
}
__device__ __forceinline__ void st_rel(unsigned int* p, unsigned int v) {
    asm volatile("st.global.release.gpu.u32 [%0], %1;" :: "l"(p), "r"(v));
}

// ---------------- TMA 1D bulk copy + mbarrier helpers -------------------------
__device__ __forceinline__ u32 smem_u32(const void* p) {
    u32 a;
    asm("{ .reg .u64 t; cvta.to.shared.u64 t, %1; cvt.u32.u64 %0, t; }"
        : "=r"(a) : "l"(p));
    return a;
}
__device__ __forceinline__ void mbar_init(u32 mbar, u32 cnt) {
    asm volatile("mbarrier.init.shared.b64 [%0], %1;" :: "r"(mbar), "r"(cnt) : "memory");
}
__device__ __forceinline__ void mbar_expect_tx(u32 mbar, u32 bytes) {
    asm volatile("mbarrier.arrive.expect_tx.shared.b64 _, [%0], %1;"
                 :: "r"(mbar), "r"(bytes) : "memory");
}
__device__ __forceinline__ void bulk_cp_g2s(u32 dst, const void* src, u32 bytes, u32 mbar) {
    asm volatile("cp.async.bulk.shared::cluster.global.mbarrier::complete_tx::bytes "
                 "[%0], [%1], %2, [%3];"
                 :: "r"(dst), "l"(src), "r"(bytes), "r"(mbar) : "memory");
}
__device__ __forceinline__ void mbar_wait(u32 mbar, u32 parity) {
    asm volatile(
        "{\n\t.reg .pred P;\n\t"
        "W_%=:\n\t"
        "mbarrier.try_wait.parity.acquire.cta.shared::cta.b64 P, [%0], %1;\n\t"
        "@!P bra W_%=;\n\t}"
        :: "r"(mbar), "r"(parity) : "memory");
}

// ---------------- persistent recurrence kernel --------------------------------
// 120 CTAs x 256 threads. GEMM: 8 warps, warp = (kz = w&3, bhalf = w>>2),
// thread tile 4b x 10r (f32x2). h tile staged by one TMA bulk copy / step.
// P gathers prefetched into regs BEFORE the GEMM (DRAM latency overlapped).
// Barrier: per-bt-group (15 CTAs), all-to-all flags, 1 L2 round trip.
#define SM_WT   (300 * 84)            // 25200 floats
#define SM_H    (BT * HID)            // 9600 floats (contiguous, stride 300)
#define SM_GP   (KZ * BT * GPS)       // 11264 floats
#define SM_FLOATS (SM_WT + SM_H + SM_GP)
#define H_TILE_BYTES (BT * HID * 4)   // 38400

__global__ __launch_bounds__(256, 1)
void lstm_persistent(const float* __restrict__ W_hh,
                     const float* __restrict__ P,
                     const int* __restrict__ ids,
                     const float* __restrict__ b_ih,
                     const float* __restrict__ b_hh,
                     float* __restrict__ hbuf,
                     float* __restrict__ hsum) {
    extern __shared__ __align__(16) float sm[];
    float* Wt  = sm;                  // [k][r], stride 84
    float* hsm = sm + SM_WT;          // [b][k], stride 300 (TMA dst)
    float* gp  = sm + SM_WT + SM_H;   // [kz][b][r], b-stride 88

    const int tid = threadIdx.x;
    const int bt  = blockIdx.x & 7;        // 0..7  (independent groups)
    const int ut  = blockIdx.x >> 3;       // 0..14
    const int b0c = bt * BT;
    const int u0  = ut * UT;

    const u32 hsm_s = smem_u32(hsm);
    const u32 mbar  = smem_u32(sm) + SM_FLOATS * 4;

    if (tid == 0) mbar_init(mbar, 1);

    // ---- load this CTA's 80 W_hh rows into smem (once), k-major ----
    for (int idx = tid; idx < RT * HID; idx += 256) {
        int r = idx / HID;
        int k = idx - r * HID;
        int g = r / UT;
        int du = r - g * UT;
        Wt[k * 84 + r] = W_hh[(g * HID + u0 + du) * HID + k];
    }

    // ---- GEMM-phase mapping: 8 warps ----
    const int lane = tid & 31;
    const int wrp  = tid >> 5;             // 0..7
    const int kz   = wrp & 3;
    const int bh   = (wrp >> 2) * 16;      // b-half base: 0 or 16
    const int gtx  = lane & 3;             // b = bh + gtx + 4*i, i<4
    const int gty  = lane >> 2;            // r = gty*10 + 2q, q<5
    const int kbeg = kz * KC;

    // ---- pointwise-phase fixed cell ownership (c, hsum in registers) ----
    int bl[3], du[3];
    bool actc[3];
#pragma unroll
    for (int c = 0; c < 3; c++) {
        int cell = tid + c * 256;
        bl[c] = cell / UT;
        du[c] = cell - bl[c] * UT;
        actc[c] = (c < 2) || (tid < 128);
    }
    float cr[3] = {0.f, 0.f, 0.f};
    float hs[3] = {0.f, 0.f, 0.f};
    float bs[3][4];
#pragma unroll
    for (int c = 0; c < 3; c++) {
#pragma unroll
        for (int g = 0; g < 4; g++) {
            int col = g * HID + u0 + du[c];
            bs[c][g] = actc[c] ? (b_ih[col] + b_hh[col]) : 0.f;
        }
    }

    __syncthreads();

    for (int t = 0; t < T_SZ; t++) {
        const float* hin_tile = hbuf + (t & 1) * (B_SZ * HID) + b0c * HID;
        float*       hout     = hbuf + ((t + 1) & 1) * (B_SZ * HID);

        // ---- kick off h-tile TMA bulk copy (contiguous 38400 B) ----
        if (tid == 0) {
            mbar_expect_tx(mbar, H_TILE_BYTES);
            bulk_cp_g2s(hsm_s, hin_tile, H_TILE_BYTES, mbar);
        }

        // ---- prefetch P gathers into registers (overlaps GEMM below) ----
        float pfA[3][4], pfB[3][4];
#pragma unroll
        for (int c = 0; c < 3; c++) {
#pragma unroll
            for (int g = 0; g < 4; g++) { pfA[c][g] = 0.f; pfB[c][g] = 0.f; }
            if (actc[c]) {
                int row = (b0c + bl[c]) * T_SZ;
                if (t != T_SZ - 1) {          // emb[T-1] zeroed (reference quirk)
                    const float* pa = P + (long long)ids[row + t] * PCOLS
                                        + u0 + du[c];
#pragma unroll
                    for (int g = 0; g < 4; g++) pfA[c][g] = pa[g * HID];
                }
                if (t != 0) {                 // emb_{-1} is zero padding
                    const float* pb = P + (long long)ids[row + t - 1] * PCOLS
                                        + GATES + u0 + du[c];
#pragma unroll
                    for (int g = 0; g < 4; g++) pfB[c][g] = pb[g * HID];
                }
            }
        }

        // ---- wait for h tile ----
        mbar_wait(mbar, (u32)(t & 1));

        // ---- gates GEMM: 32x80, 8 warps (kz x bhalf), f32x2 FMA ----
        {
            u64 acc[4][5];
#pragma unroll
            for (int i = 0; i < 4; i++)
#pragma unroll
                for (int q = 0; q < 5; q++) acc[i][q] = 0ULL;

#pragma unroll 3
            for (int k = kbeg; k < kbeg + KC; k++) {
                u64 hd[4], wd[5];
#pragma unroll
                for (int i = 0; i < 4; i++)
                    hd[i] = dup2(hsm[(bh + gtx + 4 * i) * HID + k]);
#pragma unroll
                for (int q = 0; q < 5; q++)
                    wd[q] = *(const u64*)&Wt[k * 84 + gty * 10 + 2 * q];
#pragma unroll
                for (int i = 0; i < 4; i++)
#pragma unroll
                    for (int q = 0; q < 5; q++)
                        ffma2(acc[i][q], hd[i], wd[q]);
            }
#pragma unroll
            for (int i = 0; i < 4; i++)
#pragma unroll
                for (int q = 0; q < 5; q++)
                    *(u64*)&gp[kz * (BT * GPS) + (bh + gtx + 4 * i) * GPS +
                               gty * 10 + 2 * q] = acc[i][q];
        }
        __syncthreads();

        // ---- fused cell update: gp reduce + prefetched P + activations ----
#pragma unroll
        for (int c = 0; c < 3; c++) {
            if (actc[c]) {
                float g4[4];
#pragma unroll
                for (int g = 0; g < 4; g++) {
                    float s = bs[c][g] + pfA[c][g] + pfB[c][g];
#pragma unroll
                    for (int z = 0; z < KZ; z++)
                        s += gp[z * (BT * GPS) + bl[c] * GPS + g * UT + du[c]];
                    g4[g] = s;
                }
                float ig = fsig(g4[0]);
                float fg = fsig(g4[1]);
                float gg = 2.f * fsig(2.f * g4[2]) - 1.f;   // tanh
                float og = fsig(g4[3]);
                cr[c] = fg * cr[c] + ig * gg;
                float th = 2.f * fsig(2.f * cr[c]) - 1.f;   // tanh
                float hv = og * th;
                hout[(b0c + bl[c]) * HID + u0 + du[c]] = hv;
                hs[c] += hv;
            }
        }
        __syncthreads();

        // ---- per-bt-group barrier: 15 CTAs, all-to-all flags ----
        if (tid == 0) {
            __threadfence();
            st_rel(&d_arrive[bt][ut], (u32)(t + 1));
        }
        if (tid < 15 && tid != ut) {
            while (ld_acq(&d_arrive[bt][tid]) < (u32)(t + 1)) {}
        }
        __syncthreads();
    }

    // ---- write hidden-state sums for the classifier ----
#pragma unroll
    for (int c = 0; c < 3; c++) {
        if (actc[c])
            hsum[(b0c + bl[c]) * HID + u0 + du[c]] = hs[c];
    }
}

// ---------------- classifier head: mean-pool -> dense(100) -> dense(5) -> LSM
__global__ void classifier(const float* __restrict__ hsum,
                           const float* __restrict__ W1, const float* __restrict__ b1,
                           const float* __restrict__ W2, const float* __restrict__ b2,
                           float* __restrict__ out) {
    int b = blockIdx.x;
    int tid = threadIdx.x;   // 128
    __shared__ float pooled[HID];
    __shared__ float l1s[100];
    __shared__ float l2s[NCLS];

    for (int i = tid; i < HID; i += blockDim.x)
        pooled[i] = hsum[b * HID + i] * (1.f / (float)T_SZ);
    __syncthreads();

    if (tid < 100) {
        float s = b1[tid];
        const float* wr = W1 + tid * HID;
#pragma unroll 4
        for (int k = 0; k < HID; k++) s = fmaf(pooled[k], wr[k], s);
        l1s[tid] = 1.f / (1.f + expf(-s));
    }
    __syncthreads();

    if (tid < NCLS) {
        float s = b2[tid];
        const float* wr = W2 + tid * 100;
#pragma unroll 4
        for (int k = 0; k < 100; k++) s = fmaf(l1s[k], wr[k], s);
        l2s[tid] = 1.f / (1.f + expf(-s));
    }
    __syncthreads();

    if (tid < NCLS) {
        float m = l2s[0];
#pragma unroll
        for (int j = 1; j < NCLS; j++) m = fmaxf(m, l2s[j]);
        float sum = 0.f;
#pragma unroll
        for (int j = 0; j < NCLS; j++) sum += expf(l2s[j] - m);
        out[b * NCLS + tid] = l2s[tid] - m - logf(sum);
    }
}

// ------------------------------ launch ---------------------------------------
extern "C" void kernel_launch(void* const* d_in, const int* in_sizes, int n_in,
                              void* d_out, int out_size) {
    const int*   ids  = nullptr;
    const float* glove = nullptr, *W_ih = nullptr, *W_hh = nullptr;
    const float* b_ih = nullptr, *b_hh = nullptr;
    const float* W1 = nullptr, *b1 = nullptr, *W2 = nullptr, *b2 = nullptr;

    for (int i = 0; i < n_in; i++) {
        switch (in_sizes[i]) {
            case B_SZ * T_SZ:      ids   = (const int*)d_in[i];   break;
            case VOCAB * EMB:      glove = (const float*)d_in[i]; break;
            case GATES * 600:      W_ih  = (const float*)d_in[i]; break;
            case GATES * HID:      W_hh  = (const float*)d_in[i]; break;
            case GATES:            if (!b_ih) b_ih = (const float*)d_in[i];
                                   else       b_hh = (const float*)d_in[i]; break;
            case 100 * HID:        W1 = (const float*)d_in[i]; break;
            case 100:              b1 = (const float*)d_in[i]; break;
            case NCLS * 100:       W2 = (const float*)d_in[i]; break;
            case NCLS:             b2 = (const float*)d_in[i]; break;
            default: break; // size-1 scalar (max_num_of_words) ignored
        }
    }
    if (!ids || !glove || !W_ih || !W_hh || !b_ih || !b_hh || !W1 || !b1 || !W2 || !b2)
        return;

    float *P, *Wcat, *hbuf, *hsum;
    cudaGetSymbolAddress((void**)&P,    d_P);
    cudaGetSymbolAddress((void**)&Wcat, d_Wcat);
    cudaGetSymbolAddress((void**)&hbuf, d_h);
    cudaGetSymbolAddress((void**)&hsum, d_hsum);

    static bool attr_done = false;
    if (!attr_done) {
        cudaFuncSetAttribute(lstm_persistent,
                             cudaFuncAttributeMaxDynamicSharedMemorySize,
                             SM_FLOATS * (int)sizeof(float) + 8);
        attr_done = true;
    }

    // 1) repack W_ih, zero h0 + barrier flags       [1 node]
    prep_kernel<<<(PCOLS * EMB + 255) / 256, 256>>>(W_ih, Wcat, hbuf);

    // 2) vocabulary projection P = glove @ Wcat^T   [1 node]
    {
        dim3 grid((PCOLS + TILE - 1) / TILE, (VOCAB + TILE - 1) / TILE, 1);
        sgemm_f2<<<grid, 256>>>(glove, Wcat, P,
                                VOCAB, PCOLS, EMB, EMB, EMB, PCOLS);
    }

    // 3) whole 512-step LSTM in one persistent kernel [1 node]
    lstm_persistent<<<NCTA, 256, SM_FLOATS * sizeof(float) + 8>>>(
        W_hh, P, ids, b_ih, b_hh, hbuf, hsum);

    // 4) classifier head [1 node]
    classifier<<<B_SZ, 128>>>(hsum, W1, b1, W2, b2, (float*)d_out);
}